// round 9
// baseline (speedup 1.0000x reference)
#include <cuda_runtime.h>
#include <cstdint>

#define BB 256
#define TT 1024
#define HH 128
#define II 19
#define STG_T 16
#define HSLOT 72   // padded half-slot for h buffers (bank-conflict-free)

// Scratch (device global; no runtime allocation allowed)
__device__ float g_pre[BB * TT * HH];   // layer-1 pre-activations (from proj0)

typedef unsigned long long ull;

__device__ __forceinline__ ull ffma2(ull a, ull b, ull c) {
    ull d;
    asm("fma.rn.f32x2 %0, %1, %2, %3;" : "=l"(d) : "l"(a), "l"(b), "l"(c));
    return d;
}

__device__ __forceinline__ ull fadd2(ull a, ull b) {
    ull d;
    asm("add.rn.f32x2 %0, %1, %2;" : "=l"(d) : "l"(a), "l"(b));
    return d;
}

__device__ __forceinline__ float hsum2(ull a) {
    float x, y;
    asm("mov.b64 {%0, %1}, %2;" : "=f"(x), "=f"(y) : "l"(a));
    return x + y;
}

// tanh(x) = 1 - 2/(exp(2x)+1) via approx MUFU; ~1e-6 err, saturates to +/-1
__device__ __forceinline__ float fast_tanh(float x) {
    float e;
    asm("ex2.approx.f32 %0, %1;" : "=f"(e) : "f"(x * 2.8853900817779268f));
    float r;
    asm("rcp.approx.f32 %0, %1;" : "=f"(r) : "f"(e + 1.0f));
    return fmaf(-2.0f, r, 1.0f);
}

__device__ __forceinline__ uint32_t s2u(const void* p) {
    return (uint32_t)__cvta_generic_to_shared(p);
}
// .cg -> L2 only, keeps L1 free for the W_ih1 working set
#define CP_ASYNC16CG(dst, src) \
    asm volatile("cp.async.cg.shared.global [%0], [%1], 16;" :: "r"(dst), "l"(src))
#define CP_COMMIT() asm volatile("cp.async.commit_group;" ::: "memory")
#define CP_WAIT0()  asm volatile("cp.async.wait_group 0;" ::: "memory")
#define CP_WAIT1()  asm volatile("cp.async.wait_group 1;" ::: "memory")

// volatile LDG.128 (L1-cached, NOT hoistable out of the loop -> no reg blowup)
__device__ __forceinline__ void ldg128(ull& x, ull& y, const void* p) {
    asm volatile("ld.global.nc.v2.u64 {%0, %1}, [%2];"
                 : "=l"(x), "=l"(y) : "l"(p));
}

// ---------------------------------------------------------------------------
// proj0: pre1 = x @ W_ih0^T + (b_ih0 + b_hh0).  x:[B,T,19], W:[128,19]
// ---------------------------------------------------------------------------
#define ROWS0 8
__global__ void __launch_bounds__(128) proj0_kernel(
    const float* __restrict__ x,
    const float* __restrict__ Wih,
    const float* __restrict__ bih,
    const float* __restrict__ bhh)
{
    __shared__ float xs[ROWS0 * II];
    const int j   = threadIdx.x;
    const int blk = blockIdx.x;

    float w[II];
#pragma unroll
    for (int i = 0; i < II; i++) w[i] = Wih[j * II + i];
    const float bias = bih[j] + bhh[j];

    const float* src = x + (size_t)blk * ROWS0 * II;
    for (int i = j; i < ROWS0 * II; i += 128) xs[i] = src[i];
    __syncthreads();

#pragma unroll
    for (int r = 0; r < ROWS0; r++) {
        float acc = bias;
#pragma unroll
        for (int i = 0; i < II; i++) acc += xs[r * II + i] * w[i];
        g_pre[((size_t)blk * ROWS0 + r) * HH + j] = acc;
    }
}

// ---------------------------------------------------------------------------
// fused: scan1 + proj1 + scan2 in one kernel.
// Iteration i computes, for 2 batch rows:
//   h1_i     = tanh(pre1_i + W_hh0 h1_{i-1})
//   h2_{i-1} = tanh(b2 + W_ih1 h1_{i-1} + W_hh1 h2_{i-2})
// All matvecs read only h1_{i-1}, h2_{i-2} -> independent, ONE barrier/iter.
// 128 CTAs x 256 threads (single wave). Thread pair (2j, 2j+1) = output j,
// lane owns a K-half: W_hh0/W_hh1 half-rows in regs (128 regs), W_ih1 half-row
// re-read each iter via volatile LDG.128 (64KB, L1-resident; pre1 staged with
// cp.async.cg so it bypasses L1). h exchange via padded smem slots + 1 shfl.
// Only h2 goes to global (out). g_out1 and proj1 are eliminated.
// ---------------------------------------------------------------------------
#define PS_STRIDE (STG_T * 2 * HH)

__device__ __forceinline__ void fused_prefetch(float* dst, const float* preA,
                                               const float* preB, int t0, int tid) {
    uint32_t dbase = s2u(dst);
#pragma unroll
    for (int it = 0; it < 4; it++) {
        int lin = it * 256 + tid;               // [0,1024) 16B chunks
        int c   = lin & 31;                     // chunk within 128-float row
        int pr  = lin >> 5;                     // (t,row)
        int t   = pr >> 1;
        int row = pr & 1;
        const float* src = (row ? preB : preA) + (size_t)(t0 + t) * HH + c * 4;
        CP_ASYNC16CG(dbase + lin * 16, src);
    }
}

__global__ void __launch_bounds__(256, 1) fused_kernel(
    const float* __restrict__ Whh0,
    const float* __restrict__ Wih1,
    const float* __restrict__ Whh1,
    const float* __restrict__ bih1,
    const float* __restrict__ bhh1,
    float* __restrict__ out)
{
    __shared__ __align__(16) float ps[2 * PS_STRIDE];       // staged pre1, 2 rows
    __shared__ __align__(16) float h1s[2][2][2 * HSLOT];    // [buf][row][slot]
    __shared__ __align__(16) float h2s[2][2][2 * HSLOT];

    const int tid  = threadIdx.x;
    const int j    = tid >> 1;
    const int half = tid & 1;
    const int bA   = blockIdx.x * 2;
    const int bB   = bA + 1;

    const float* preA = g_pre + (size_t)bA * TT * HH;
    const float* preB = g_pre + (size_t)bB * TT * HH;

    // stages 0,1 in flight before the long-latency W loads
    fused_prefetch(&ps[0],         preA, preB, 0,     tid);
    CP_COMMIT();
    fused_prefetch(&ps[PS_STRIDE], preA, preB, STG_T, tid);
    CP_COMMIT();

    // register-resident W halves: W_hh0 and W_hh1 row j, this lane's K-half
    ull w0[32], w1[32];
    {
        const ulonglong2* p0 = (const ulonglong2*)(Whh0 + j * HH + half * 64);
#pragma unroll
        for (int q = 0; q < 16; q++) {
            ulonglong2 t0 = p0[q];
            w0[2 * q] = t0.x; w0[2 * q + 1] = t0.y;
        }
        const ulonglong2* p1 = (const ulonglong2*)(Whh1 + j * HH + half * 64);
#pragma unroll
        for (int q = 0; q < 16; q++) {
            ulonglong2 t1 = p1[q];
            w1[2 * q] = t1.x; w1[2 * q + 1] = t1.y;
        }
    }
    const char* wih = (const char*)(Wih1 + j * HH + half * 64);  // 64 floats
    const float b2 = bih1[j] + bhh1[j];

    float* orowA = out + (size_t)bA * TT * HH + j;
    float* orowB = out + (size_t)bB * TT * HH + j;

    // zero-init h buffers (h1_{-1} = 0; h2_{-1} and h2_{-2} = 0)
    {
        float* z1 = &h1s[0][0][0];
        float* z2 = &h2s[0][0][0];
        for (int z = tid; z < 2 * 2 * 2 * HSLOT; z += 256) { z1[z] = 0.0f; z2[z] = 0.0f; }
    }
    const int hw = j + ((j >> 6) << 3);   // write slot of output j
    __syncthreads();

    const int nst = TT / STG_T;

#pragma unroll 1
    for (int s = 0; s < nst; s++) {
        if (s + 1 < nst) { CP_WAIT1(); } else { CP_WAIT0(); }
        __syncthreads();

        const float* pst = &ps[(s & 1) * PS_STRIDE];
        const int tbase = s * STG_T;

#pragma unroll 1
        for (int tl = 0; tl < STG_T; tl += 2) {
#pragma unroll
            for (int sub = 0; sub < 2; sub++) {
                const int ii  = tbase + tl + sub;
                const int rb  = ii & 1;          // read buffer
                const int wb  = rb ^ 1;          // write buffer

                float pA = pst[((tl + sub) * 2 + 0) * HH + j];
                float pB = pst[((tl + sub) * 2 + 1) * HH + j];

                const ulonglong2* h1A = (const ulonglong2*)&h1s[rb][0][half * HSLOT];
                const ulonglong2* h1B = (const ulonglong2*)&h1s[rb][1][half * HSLOT];
                const ulonglong2* h2A = (const ulonglong2*)&h2s[rb][0][half * HSLOT];
                const ulonglong2* h2B = (const ulonglong2*)&h2s[rb][1][half * HSLOT];

                ull aA0 = 0, aA1 = 0, cA0 = 0, cA1 = 0;
                ull aB0 = 0, aB1 = 0, cB0 = 0, cB1 = 0;
#pragma unroll
                for (int q = 0; q < 8; q++) {
                    ulonglong2 x1A0 = h1A[2 * q], x1A1 = h1A[2 * q + 1];
                    ulonglong2 x1B0 = h1B[2 * q], x1B1 = h1B[2 * q + 1];
                    ull wv0, wv1, wv2, wv3;
                    ldg128(wv0, wv1, wih + q * 32);
                    ldg128(wv2, wv3, wih + q * 32 + 16);
                    ulonglong2 x2A0 = h2A[2 * q], x2A1 = h2A[2 * q + 1];
                    ulonglong2 x2B0 = h2B[2 * q], x2B1 = h2B[2 * q + 1];
                    // layer-1 recurrence (W_hh0)
                    aA0 = ffma2(x1A0.x, w0[4 * q],     aA0);
                    aA1 = ffma2(x1A0.y, w0[4 * q + 1], aA1);
                    aA0 = ffma2(x1A1.x, w0[4 * q + 2], aA0);
                    aA1 = ffma2(x1A1.y, w0[4 * q + 3], aA1);
                    aB0 = ffma2(x1B0.x, w0[4 * q],     aB0);
                    aB1 = ffma2(x1B0.y, w0[4 * q + 1], aB1);
                    aB0 = ffma2(x1B1.x, w0[4 * q + 2], aB0);
                    aB1 = ffma2(x1B1.y, w0[4 * q + 3], aB1);
                    // layer-2 input projection (W_ih1, reuses h1 regs)
                    cA0 = ffma2(x1A0.x, wv0, cA0);
                    cA1 = ffma2(x1A0.y, wv1, cA1);
                    cA0 = ffma2(x1A1.x, wv2, cA0);
                    cA1 = ffma2(x1A1.y, wv3, cA1);
                    cB0 = ffma2(x1B0.x, wv0, cB0);
                    cB1 = ffma2(x1B0.y, wv1, cB1);
                    cB0 = ffma2(x1B1.x, wv2, cB0);
                    cB1 = ffma2(x1B1.y, wv3, cB1);
                    // layer-2 recurrence (W_hh1)
                    cA0 = ffma2(x2A0.x, w1[4 * q],     cA0);
                    cA1 = ffma2(x2A0.y, w1[4 * q + 1], cA1);
                    cA0 = ffma2(x2A1.x, w1[4 * q + 2], cA0);
                    cA1 = ffma2(x2A1.y, w1[4 * q + 3], cA1);
                    cB0 = ffma2(x2B0.x, w1[4 * q],     cB0);
                    cB1 = ffma2(x2B0.y, w1[4 * q + 1], cB1);
                    cB0 = ffma2(x2B1.x, w1[4 * q + 2], cB0);
                    cB1 = ffma2(x2B1.y, w1[4 * q + 3], cB1);
                }
                float dA0 = hsum2(fadd2(aA0, aA1));
                float dA2 = hsum2(fadd2(cA0, cA1));
                float dB0 = hsum2(fadd2(aB0, aB1));
                float dB2 = hsum2(fadd2(cB0, cB1));
                dA0 += __shfl_xor_sync(0xffffffffu, dA0, 1);
                dA2 += __shfl_xor_sync(0xffffffffu, dA2, 1);
                dB0 += __shfl_xor_sync(0xffffffffu, dB0, 1);
                dB2 += __shfl_xor_sync(0xffffffffu, dB2, 1);

                float h1Av = fast_tanh(pA + dA0);
                float h1Bv = fast_tanh(pB + dB0);
                float t2A  = fast_tanh(b2 + dA2);
                float t2B  = fast_tanh(b2 + dB2);

                // h1 stores (always): lane0 -> row A, lane1 -> row B
                if (!half) h1s[wb][0][hw] = h1Av;
                else       h1s[wb][1][hw] = h1Bv;
                // h2 stores (skip ii==0: keeps h2_{-1}=0, no OOB global write)
                if (ii > 0) {
                    if (!half) {
                        h2s[wb][0][hw] = t2A;
                        orowA[(size_t)(ii - 1) * HH] = t2A;
                    } else {
                        h2s[wb][1][hw] = t2B;
                        orowB[(size_t)(ii - 1) * HH] = t2B;
                    }
                }
                __syncthreads();
            }
        }

        // refill stage s+2 into the buffer just consumed
        if (s + 2 < nst) {
            fused_prefetch(&ps[(s & 1) * PS_STRIDE], preA, preB, (s + 2) * STG_T, tid);
        }
        CP_COMMIT();
    }

    // epilogue: h2_{1023} from h1_{1023} (h1s[0]) and h2_{1022} (h2s[0])
    {
        const ulonglong2* h1A = (const ulonglong2*)&h1s[0][0][half * HSLOT];
        const ulonglong2* h1B = (const ulonglong2*)&h1s[0][1][half * HSLOT];
        const ulonglong2* h2A = (const ulonglong2*)&h2s[0][0][half * HSLOT];
        const ulonglong2* h2B = (const ulonglong2*)&h2s[0][1][half * HSLOT];
        ull cA0 = 0, cA1 = 0, cB0 = 0, cB1 = 0;
#pragma unroll
        for (int q = 0; q < 8; q++) {
            ulonglong2 x1A0 = h1A[2 * q], x1A1 = h1A[2 * q + 1];
            ulonglong2 x1B0 = h1B[2 * q], x1B1 = h1B[2 * q + 1];
            ull wv0, wv1, wv2, wv3;
            ldg128(wv0, wv1, wih + q * 32);
            ldg128(wv2, wv3, wih + q * 32 + 16);
            ulonglong2 x2A0 = h2A[2 * q], x2A1 = h2A[2 * q + 1];
            ulonglong2 x2B0 = h2B[2 * q], x2B1 = h2B[2 * q + 1];
            cA0 = ffma2(x1A0.x, wv0, cA0);
            cA1 = ffma2(x1A0.y, wv1, cA1);
            cA0 = ffma2(x1A1.x, wv2, cA0);
            cA1 = ffma2(x1A1.y, wv3, cA1);
            cB0 = ffma2(x1B0.x, wv0, cB0);
            cB1 = ffma2(x1B0.y, wv1, cB1);
            cB0 = ffma2(x1B1.x, wv2, cB0);
            cB1 = ffma2(x1B1.y, wv3, cB1);
            cA0 = ffma2(x2A0.x, w1[4 * q],     cA0);
            cA1 = ffma2(x2A0.y, w1[4 * q + 1], cA1);
            cA0 = ffma2(x2A1.x, w1[4 * q + 2], cA0);
            cA1 = ffma2(x2A1.y, w1[4 * q + 3], cA1);
            cB0 = ffma2(x2B0.x, w1[4 * q],     cB0);
            cB1 = ffma2(x2B0.y, w1[4 * q + 1], cB1);
            cB0 = ffma2(x2B1.x, w1[4 * q + 2], cB0);
            cB1 = ffma2(x2B1.y, w1[4 * q + 3], cB1);
        }
        float dA2 = hsum2(fadd2(cA0, cA1));
        float dB2 = hsum2(fadd2(cB0, cB1));
        dA2 += __shfl_xor_sync(0xffffffffu, dA2, 1);
        dB2 += __shfl_xor_sync(0xffffffffu, dB2, 1);
        float t2A = fast_tanh(b2 + dA2);
        float t2B = fast_tanh(b2 + dB2);
        if (!half) orowA[(size_t)(TT - 1) * HH] = t2A;
        else       orowB[(size_t)(TT - 1) * HH] = t2B;
    }
}

// ---------------------------------------------------------------------------
extern "C" void kernel_launch(void* const* d_in, const int* in_sizes, int n_in,
                              void* d_out, int out_size)
{
    const float* x     = (const float*)d_in[0];
    const float* Wih0  = (const float*)d_in[1];
    const float* Whh0  = (const float*)d_in[2];
    const float* bih0  = (const float*)d_in[3];
    const float* bhh0  = (const float*)d_in[4];
    const float* Wih1  = (const float*)d_in[5];
    const float* Whh1  = (const float*)d_in[6];
    const float* bih1  = (const float*)d_in[7];
    const float* bhh1  = (const float*)d_in[8];
    float* out = (float*)d_out;

    proj0_kernel<<<BB * TT / ROWS0, 128>>>(x, Wih0, bih0, bhh0);
    fused_kernel<<<BB / 2, 256>>>(Whh0, Wih1, Whh1, bih1, bhh1, out);
}

// round 10
// speedup vs baseline: 1.8582x; 1.8582x over previous
#include <cuda_runtime.h>
#include <cstdint>

#define BB 256
#define TT 1024
#define HH 128
#define II 19
#define STG_T 16   // timesteps per cp.async stage in scan
#define HSLOT 72   // padded half-slot offset in h buffers

// Scratch (device globals; no runtime allocation allowed)
__device__ float g_pre[BB * TT * HH];   // pre-activations for current layer
__device__ float g_out1[BB * TT * HH];  // layer-0 hidden outputs

typedef unsigned long long ull;

__device__ __forceinline__ ull ffma2(ull a, ull b, ull c) {
    ull d;
    asm("fma.rn.f32x2 %0, %1, %2, %3;" : "=l"(d) : "l"(a), "l"(b), "l"(c));
    return d;
}

__device__ __forceinline__ ull fadd2(ull a, ull b) {
    ull d;
    asm("add.rn.f32x2 %0, %1, %2;" : "=l"(d) : "l"(a), "l"(b));
    return d;
}

__device__ __forceinline__ float hsum2(ull a) {
    float x, y;
    asm("mov.b64 {%0, %1}, %2;" : "=f"(x), "=f"(y) : "l"(a));
    return x + y;
}

// tanh(x) = 1 - 2/(exp(2x)+1) via approx MUFU; ~1e-6 err, saturates to +/-1
__device__ __forceinline__ float fast_tanh(float x) {
    float e;
    asm("ex2.approx.f32 %0, %1;" : "=f"(e) : "f"(x * 2.8853900817779268f));
    float r;
    asm("rcp.approx.f32 %0, %1;" : "=f"(r) : "f"(e + 1.0f));
    return fmaf(-2.0f, r, 1.0f);
}

__device__ __forceinline__ uint32_t s2u(const void* p) {
    return (uint32_t)__cvta_generic_to_shared(p);
}
#define CP_ASYNC16(dst, src) \
    asm volatile("cp.async.ca.shared.global [%0], [%1], 16;" :: "r"(dst), "l"(src))
#define CP_COMMIT() asm volatile("cp.async.commit_group;" ::: "memory")
#define CP_WAIT0()  asm volatile("cp.async.wait_group 0;" ::: "memory")
#define CP_WAIT1()  asm volatile("cp.async.wait_group 1;" ::: "memory")

// ---------------------------------------------------------------------------
// proj0: pre = x @ W_ih0^T + (b_ih0 + b_hh0).  x:[B,T,19], W:[128,19]
// ---------------------------------------------------------------------------
#define ROWS0 8
__global__ void __launch_bounds__(128) proj0_kernel(
    const float* __restrict__ x,
    const float* __restrict__ Wih,
    const float* __restrict__ bih,
    const float* __restrict__ bhh)
{
    __shared__ float xs[ROWS0 * II];
    const int j   = threadIdx.x;
    const int blk = blockIdx.x;

    float w[II];
#pragma unroll
    for (int i = 0; i < II; i++) w[i] = Wih[j * II + i];
    const float bias = bih[j] + bhh[j];

    const float* src = x + (size_t)blk * ROWS0 * II;
    for (int i = j; i < ROWS0 * II; i += 128) xs[i] = src[i];
    __syncthreads();

#pragma unroll
    for (int r = 0; r < ROWS0; r++) {
        float acc = bias;
#pragma unroll
        for (int i = 0; i < II; i++) acc += xs[r * II + i] * w[i];
        g_pre[((size_t)blk * ROWS0 + r) * HH + j] = acc;
    }
}

// ---------------------------------------------------------------------------
// proj1 (persistent): pre = out1 @ W_ih1^T + bias.  out1:[B*T,128], W:[128,128]
// 296 CTAs; W row per thread loaded ONCE into 64 packed regs; input tiles
// double-buffered via cp.async.
// ---------------------------------------------------------------------------
#define ROWS1 16
#define NT1   (BB * TT / ROWS1)
#define PJ1_GRID 296

__device__ __forceinline__ void pj1_prefetch(float* dst, int tile, int j) {
    uint32_t dbase = s2u(dst);
    const float* src = g_out1 + (size_t)tile * ROWS1 * HH;
#pragma unroll
    for (int it = 0; it < 4; it++) {
        int lin = it * 128 + j;                 // [0,512) 16B chunks
        CP_ASYNC16(dbase + lin * 16, src + lin * 4);
    }
}

__global__ void __launch_bounds__(128, 2) proj1_kernel(
    const float* __restrict__ Wih,
    const float* __restrict__ bih,
    const float* __restrict__ bhh)
{
    __shared__ __align__(16) float in_s[2][ROWS1 * HH];
    const int j = threadIdx.x;

    int t = blockIdx.x;
    if (t < NT1) pj1_prefetch(in_s[0], t, j);
    CP_COMMIT();

    ull w[64];
    {
        const ulonglong2* wr = (const ulonglong2*)(Wih + j * HH);
#pragma unroll
        for (int q = 0; q < 32; q++) {
            ulonglong2 tt = wr[q];
            w[2 * q]     = tt.x;
            w[2 * q + 1] = tt.y;
        }
    }
    const float bias = bih[j] + bhh[j];

    int buf = 0;
#pragma unroll 1
    while (t < NT1) {
        const int tn = t + PJ1_GRID;
        CP_WAIT0();
        __syncthreads();
        if (tn < NT1) { pj1_prefetch(in_s[buf ^ 1], tn, j); }
        CP_COMMIT();

        const float* ins = in_s[buf];
#pragma unroll 1
        for (int r = 0; r < ROWS1; r += 4) {
            const ulonglong2* h0 = (const ulonglong2*)(ins + (r + 0) * HH);
            const ulonglong2* h1 = (const ulonglong2*)(ins + (r + 1) * HH);
            const ulonglong2* h2 = (const ulonglong2*)(ins + (r + 2) * HH);
            const ulonglong2* h3 = (const ulonglong2*)(ins + (r + 3) * HH);
            ull a0 = 0, a1 = 0, a2 = 0, a3 = 0;
            ull b0 = 0, b1 = 0, b2 = 0, b3 = 0;
            ull c0 = 0, c1 = 0, c2 = 0, c3 = 0;
            ull d0 = 0, d1 = 0, d2 = 0, d3 = 0;
#pragma unroll
            for (int q = 0; q < 16; q++) {
                ulonglong2 vA0 = h0[2 * q]; ulonglong2 vA1 = h0[2 * q + 1];
                ulonglong2 vB0 = h1[2 * q]; ulonglong2 vB1 = h1[2 * q + 1];
                ulonglong2 vC0 = h2[2 * q]; ulonglong2 vC1 = h2[2 * q + 1];
                ulonglong2 vD0 = h3[2 * q]; ulonglong2 vD1 = h3[2 * q + 1];
                a0 = ffma2(vA0.x, w[4 * q],     a0);
                b0 = ffma2(vB0.x, w[4 * q],     b0);
                c0 = ffma2(vC0.x, w[4 * q],     c0);
                d0 = ffma2(vD0.x, w[4 * q],     d0);
                a1 = ffma2(vA0.y, w[4 * q + 1], a1);
                b1 = ffma2(vB0.y, w[4 * q + 1], b1);
                c1 = ffma2(vC0.y, w[4 * q + 1], c1);
                d1 = ffma2(vD0.y, w[4 * q + 1], d1);
                a2 = ffma2(vA1.x, w[4 * q + 2], a2);
                b2 = ffma2(vB1.x, w[4 * q + 2], b2);
                c2 = ffma2(vC1.x, w[4 * q + 2], c2);
                d2 = ffma2(vD1.x, w[4 * q + 2], d2);
                a3 = ffma2(vA1.y, w[4 * q + 3], a3);
                b3 = ffma2(vB1.y, w[4 * q + 3], b3);
                c3 = ffma2(vC1.y, w[4 * q + 3], c3);
                d3 = ffma2(vD1.y, w[4 * q + 3], d3);
            }
            ull sa = fadd2(fadd2(a0, a1), fadd2(a2, a3));
            ull sb = fadd2(fadd2(b0, b1), fadd2(b2, b3));
            ull sc = fadd2(fadd2(c0, c1), fadd2(c2, c3));
            ull sd = fadd2(fadd2(d0, d1), fadd2(d2, d3));
            size_t base = ((size_t)t * ROWS1 + r) * HH + j;
            g_pre[base]          = bias + hsum2(sa);
            g_pre[base + HH]     = bias + hsum2(sb);
            g_pre[base + 2 * HH] = bias + hsum2(sc);
            g_pre[base + 3 * HH] = bias + hsum2(sd);
        }
        t = tn;
        buf ^= 1;
    }
}

// ---------------------------------------------------------------------------
// scan: h_t = tanh(pre_t + W_hh h_{t-1}).  ONE batch row per CTA, 256 CTAs x
// 256 threads, 2 CTAs/SM (launch_bounds caps regs at 128). Pair K-split:
// lanes (2j, 2j+1) compute output j, each owning HALF of W_hh row j in 32
// packed regs; halves combine with one shfl.bfly. Short FFMA stream (~64 cyc)
// + 4 warps/SMSP in 2 INDEPENDENT barrier groups -> stall hiding.
// Even lane stores h to shared, odd lane stores the output to global.
// pre staged by cp.async in double-buffered 16-step stages.
// outp == nullptr -> write g_out1 (layer 0), else write outp (layer 1).
// ---------------------------------------------------------------------------
__device__ __forceinline__ void scan_prefetch(float* dst, const float* pre,
                                              int t0, int tid) {
    uint32_t dbase = s2u(dst);
#pragma unroll
    for (int it = 0; it < 2; it++) {
        int lin = it * 256 + tid;               // [0,512) 16B chunks
        int tt  = lin >> 5;                     // timestep within stage
        int c   = lin & 31;                     // 16B chunk within row
        CP_ASYNC16(dbase + lin * 16, pre + (size_t)(t0 + tt) * HH + c * 4);
    }
}

// half-row dot: 32 ffma2 over 8 chains, reduced to one float
__device__ __forceinline__ float half_dot(const float* hbase, const ull* w) {
    const ulonglong2* h2 = (const ulonglong2*)hbase;
    ull a0 = 0, a1 = 0, a2 = 0, a3 = 0, a4 = 0, a5 = 0, a6 = 0, a7 = 0;
#pragma unroll
    for (int q = 0; q < 4; q++) {
        ulonglong2 v0 = h2[4 * q];
        ulonglong2 v1 = h2[4 * q + 1];
        ulonglong2 v2 = h2[4 * q + 2];
        ulonglong2 v3 = h2[4 * q + 3];
        a0 = ffma2(v0.x, w[8 * q],     a0);
        a1 = ffma2(v0.y, w[8 * q + 1], a1);
        a2 = ffma2(v1.x, w[8 * q + 2], a2);
        a3 = ffma2(v1.y, w[8 * q + 3], a3);
        a4 = ffma2(v2.x, w[8 * q + 4], a4);
        a5 = ffma2(v2.y, w[8 * q + 5], a5);
        a6 = ffma2(v3.x, w[8 * q + 6], a6);
        a7 = ffma2(v3.y, w[8 * q + 7], a7);
    }
    ull s = fadd2(fadd2(fadd2(a0, a1), fadd2(a2, a3)),
                  fadd2(fadd2(a4, a5), fadd2(a6, a7)));
    return hsum2(s);
}

__global__ void __launch_bounds__(256, 2) scan_kernel(
    const float* __restrict__ Whh,
    float* __restrict__ outp)
{
    __shared__ __align__(16) float hs[2][2 * HSLOT];     // [buf][padded h]
    __shared__ __align__(16) float ps[2][STG_T * HH];    // staged pre
    const int tid  = threadIdx.x;
    const int j    = tid >> 1;       // output neuron [0,128)
    const int half = tid & 1;        // K-half owned by this lane
    const int b    = blockIdx.x;

    const float* pre = g_pre + (size_t)b * TT * HH;

    // stages 0 and 1 in flight before the long-latency W load
    scan_prefetch(ps[0], pre, 0, tid);
    CP_COMMIT();
    scan_prefetch(ps[1], pre, STG_T, tid);
    CP_COMMIT();

    // half of W_hh row j: 64 floats = 32 packed pairs
    ull w[32];
    {
        const ulonglong2* wr = (const ulonglong2*)(Whh + j * HH + half * 64);
#pragma unroll
        for (int q = 0; q < 16; q++) {
            ulonglong2 t = wr[q];
            w[2 * q]     = t.x;
            w[2 * q + 1] = t.y;
        }
    }

    float* out  = outp ? outp : g_out1;
    float* orow = out + (size_t)b * TT * HH + j;
    const int hoff  = half * HSLOT;          // where this lane READS its half
    const int hmapj = j + ((j >> 6) << 3);   // where output j is STORED

    if (!half) hs[0][hmapj] = 0.0f;
    __syncthreads();

    const int nst = TT / STG_T;
#pragma unroll 1
    for (int s = 0; s < nst; s++) {
        const int buf = s & 1;
        if (s + 1 < nst) { CP_WAIT1(); } else { CP_WAIT0(); }
        __syncthreads();

        const float* pst = ps[buf];
        const int tbase = s * STG_T;
#pragma unroll 1
        for (int tl = 0; tl < STG_T; tl += 2) {
            {   // even step: hs[0] -> hs[1]
                float p    = pst[tl * HH + j];
                float part = half_dot(&hs[0][hoff], w);
                float tot  = part + __shfl_xor_sync(0xffffffffu, part, 1);
                float hn   = fast_tanh(p + tot);
                if (!half) hs[1][hmapj] = hn;
                else       orow[(size_t)(tbase + tl) * HH] = hn;
                __syncthreads();
            }
            {   // odd step: hs[1] -> hs[0]
                float p    = pst[(tl + 1) * HH + j];
                float part = half_dot(&hs[1][hoff], w);
                float tot  = part + __shfl_xor_sync(0xffffffffu, part, 1);
                float hn   = fast_tanh(p + tot);
                if (!half) hs[0][hmapj] = hn;
                else       orow[(size_t)(tbase + tl + 1) * HH] = hn;
                __syncthreads();
            }
        }

        // refill stage s+2 into the buffer just consumed
        if (s + 2 < nst) {
            scan_prefetch(ps[buf], pre, (s + 2) * STG_T, tid);
        }
        CP_COMMIT();
    }
}

// ---------------------------------------------------------------------------
extern "C" void kernel_launch(void* const* d_in, const int* in_sizes, int n_in,
                              void* d_out, int out_size)
{
    const float* x     = (const float*)d_in[0];
    const float* Wih0  = (const float*)d_in[1];
    const float* Whh0  = (const float*)d_in[2];
    const float* bih0  = (const float*)d_in[3];
    const float* bhh0  = (const float*)d_in[4];
    const float* Wih1  = (const float*)d_in[5];
    const float* Whh1  = (const float*)d_in[6];
    const float* bih1  = (const float*)d_in[7];
    const float* bhh1  = (const float*)d_in[8];
    float* out = (float*)d_out;

    // layer 0
    proj0_kernel<<<BB * TT / ROWS0, 128>>>(x, Wih0, bih0, bhh0);
    scan_kernel<<<BB, 256>>>(Whh0, nullptr);

    // layer 1
    proj1_kernel<<<PJ1_GRID, 128>>>(Wih1, bih1, bhh1);
    scan_kernel<<<BB, 256>>>(Whh1, out);
}

// round 11
// speedup vs baseline: 2.1565x; 1.1605x over previous
#include <cuda_runtime.h>
#include <cstdint>

#define BB 256
#define TT 1024
#define HH 128
#define II 19
#define STG_T 16   // timesteps per cp.async stage in scan

// Scratch (device globals; no runtime allocation allowed)
__device__ float g_pre[BB * TT * HH];   // pre-activations for current layer
__device__ float g_out1[BB * TT * HH];  // layer-0 hidden outputs

typedef unsigned long long ull;

__device__ __forceinline__ ull ffma2(ull a, ull b, ull c) {
    ull d;
    asm("fma.rn.f32x2 %0, %1, %2, %3;" : "=l"(d) : "l"(a), "l"(b), "l"(c));
    return d;
}

__device__ __forceinline__ ull fadd2(ull a, ull b) {
    ull d;
    asm("add.rn.f32x2 %0, %1, %2;" : "=l"(d) : "l"(a), "l"(b));
    return d;
}

__device__ __forceinline__ float hsum2(ull a) {
    float x, y;
    asm("mov.b64 {%0, %1}, %2;" : "=f"(x), "=f"(y) : "l"(a));
    return x + y;
}

// single-MUFU tanh (sm_75+). max err ~5e-4; RNN error transfer measured ~0.5x
// -> final rel_err ~1-3e-4, well under the 1e-3 gate.
__device__ __forceinline__ float fast_tanh(float x) {
    float r;
    asm("tanh.approx.f32 %0, %1;" : "=f"(r) : "f"(x));
    return r;
}

__device__ __forceinline__ uint32_t s2u(const void* p) {
    return (uint32_t)__cvta_generic_to_shared(p);
}
#define CP_ASYNC16(dst, src) \
    asm volatile("cp.async.ca.shared.global [%0], [%1], 16;" :: "r"(dst), "l"(src))
#define CP_COMMIT() asm volatile("cp.async.commit_group;" ::: "memory")
#define CP_WAIT0()  asm volatile("cp.async.wait_group 0;" ::: "memory")
#define CP_WAIT1()  asm volatile("cp.async.wait_group 1;" ::: "memory")

// ---------------------------------------------------------------------------
// proj0: pre = x @ W_ih0^T + (b_ih0 + b_hh0).  x:[B,T,19], W:[128,19]
// ---------------------------------------------------------------------------
#define ROWS0 8
__global__ void __launch_bounds__(128) proj0_kernel(
    const float* __restrict__ x,
    const float* __restrict__ Wih,
    const float* __restrict__ bih,
    const float* __restrict__ bhh)
{
    __shared__ float xs[ROWS0 * II];
    const int j   = threadIdx.x;
    const int blk = blockIdx.x;

    float w[II];
#pragma unroll
    for (int i = 0; i < II; i++) w[i] = Wih[j * II + i];
    const float bias = bih[j] + bhh[j];

    const float* src = x + (size_t)blk * ROWS0 * II;
    for (int i = j; i < ROWS0 * II; i += 128) xs[i] = src[i];
    __syncthreads();

#pragma unroll
    for (int r = 0; r < ROWS0; r++) {
        float acc = bias;
#pragma unroll
        for (int i = 0; i < II; i++) acc += xs[r * II + i] * w[i];
        g_pre[((size_t)blk * ROWS0 + r) * HH + j] = acc;
    }
}

// ---------------------------------------------------------------------------
// proj1 (persistent): pre = out1 @ W_ih1^T + bias.  out1:[B*T,128], W:[128,128]
// 296 CTAs; W row per thread loaded ONCE into 64 packed regs; 32-row input
// tiles double-buffered via cp.async (copy of tile k+1 overlaps compute of k).
// ---------------------------------------------------------------------------
#define ROWS1 32
#define NT1   (BB * TT / ROWS1)
#define PJ1_GRID 296

__device__ __forceinline__ void pj1_prefetch(float* dst, int tile, int j) {
    uint32_t dbase = s2u(dst);
    const float* src = g_out1 + (size_t)tile * ROWS1 * HH;
#pragma unroll
    for (int it = 0; it < ROWS1 * HH / 4 / 128; it++) {   // 8 iters
        int lin = it * 128 + j;                 // [0,1024) 16B chunks
        CP_ASYNC16(dbase + lin * 16, src + lin * 4);
    }
}

__global__ void __launch_bounds__(128, 2) proj1_kernel(
    const float* __restrict__ Wih,
    const float* __restrict__ bih,
    const float* __restrict__ bhh)
{
    __shared__ __align__(16) float in_s[2][ROWS1 * HH];
    const int j = threadIdx.x;

    int t = blockIdx.x;
    if (t < NT1) pj1_prefetch(in_s[0], t, j);
    CP_COMMIT();

    ull w[64];
    {
        const ulonglong2* wr = (const ulonglong2*)(Wih + j * HH);
#pragma unroll
        for (int q = 0; q < 32; q++) {
            ulonglong2 tt = wr[q];
            w[2 * q]     = tt.x;
            w[2 * q + 1] = tt.y;
        }
    }
    const float bias = bih[j] + bhh[j];

    int buf = 0;
#pragma unroll 1
    while (t < NT1) {
        const int tn = t + PJ1_GRID;
        CP_WAIT0();
        __syncthreads();
        if (tn < NT1) { pj1_prefetch(in_s[buf ^ 1], tn, j); }
        CP_COMMIT();

        const float* ins = in_s[buf];
#pragma unroll 1
        for (int r = 0; r < ROWS1; r += 4) {
            const ulonglong2* h0 = (const ulonglong2*)(ins + (r + 0) * HH);
            const ulonglong2* h1 = (const ulonglong2*)(ins + (r + 1) * HH);
            const ulonglong2* h2 = (const ulonglong2*)(ins + (r + 2) * HH);
            const ulonglong2* h3 = (const ulonglong2*)(ins + (r + 3) * HH);
            ull a0 = 0, a1 = 0, a2 = 0, a3 = 0;
            ull b0 = 0, b1 = 0, b2 = 0, b3 = 0;
            ull c0 = 0, c1 = 0, c2 = 0, c3 = 0;
            ull d0 = 0, d1 = 0, d2 = 0, d3 = 0;
#pragma unroll
            for (int q = 0; q < 16; q++) {
                ulonglong2 vA0 = h0[2 * q]; ulonglong2 vA1 = h0[2 * q + 1];
                ulonglong2 vB0 = h1[2 * q]; ulonglong2 vB1 = h1[2 * q + 1];
                ulonglong2 vC0 = h2[2 * q]; ulonglong2 vC1 = h2[2 * q + 1];
                ulonglong2 vD0 = h3[2 * q]; ulonglong2 vD1 = h3[2 * q + 1];
                a0 = ffma2(vA0.x, w[4 * q],     a0);
                b0 = ffma2(vB0.x, w[4 * q],     b0);
                c0 = ffma2(vC0.x, w[4 * q],     c0);
                d0 = ffma2(vD0.x, w[4 * q],     d0);
                a1 = ffma2(vA0.y, w[4 * q + 1], a1);
                b1 = ffma2(vB0.y, w[4 * q + 1], b1);
                c1 = ffma2(vC0.y, w[4 * q + 1], c1);
                d1 = ffma2(vD0.y, w[4 * q + 1], d1);
                a2 = ffma2(vA1.x, w[4 * q + 2], a2);
                b2 = ffma2(vB1.x, w[4 * q + 2], b2);
                c2 = ffma2(vC1.x, w[4 * q + 2], c2);
                d2 = ffma2(vD1.x, w[4 * q + 2], d2);
                a3 = ffma2(vA1.y, w[4 * q + 3], a3);
                b3 = ffma2(vB1.y, w[4 * q + 3], b3);
                c3 = ffma2(vC1.y, w[4 * q + 3], c3);
                d3 = ffma2(vD1.y, w[4 * q + 3], d3);
            }
            ull sa = fadd2(fadd2(a0, a1), fadd2(a2, a3));
            ull sb = fadd2(fadd2(b0, b1), fadd2(b2, b3));
            ull sc = fadd2(fadd2(c0, c1), fadd2(c2, c3));
            ull sd = fadd2(fadd2(d0, d1), fadd2(d2, d3));
            size_t base = ((size_t)t * ROWS1 + r) * HH + j;
            g_pre[base]          = bias + hsum2(sa);
            g_pre[base + HH]     = bias + hsum2(sb);
            g_pre[base + 2 * HH] = bias + hsum2(sc);
            g_pre[base + 3 * HH] = bias + hsum2(sd);
        }
        t = tn;
        buf ^= 1;
    }
}

// ---------------------------------------------------------------------------
// scan: h_t = tanh(pre_t + W_hh h_{t-1}).  ONE batch row per CTA, 256 CTAs,
// 2 CTAs/SM: two independent recurrences per SMSP hide each other's serial
// tails. W_hh row j register-resident (64 packed regs); pre staged by
// cp.async in double-buffered 16-step stages; tanh = single MUFU op.
// outp == nullptr -> write g_out1 (layer 0), else write outp (layer 1).
// ---------------------------------------------------------------------------
__device__ __forceinline__ void scan_prefetch(float* dst, const float* pre,
                                              int t0, int j) {
    uint32_t dbase = s2u(dst);
#pragma unroll
    for (int it = 0; it < 4; it++) {
        int lin = it * 128 + j;                 // [0,512) 16B chunks
        int tt  = lin >> 5;                     // timestep within stage
        int c   = lin & 31;                     // 16B chunk within row
        CP_ASYNC16(dbase + lin * 16, pre + (size_t)(t0 + tt) * HH + c * 4);
    }
}

__device__ __forceinline__ float scan_step1(const float* hp, const ull* w, float p) {
    const ulonglong2* h2 = (const ulonglong2*)hp;
    ull a0 = 0, a1 = 0, a2 = 0, a3 = 0, a4 = 0, a5 = 0, a6 = 0, a7 = 0;
#pragma unroll
    for (int q = 0; q < 8; q++) {
        ulonglong2 v0 = h2[4 * q];
        ulonglong2 v1 = h2[4 * q + 1];
        ulonglong2 v2 = h2[4 * q + 2];
        ulonglong2 v3 = h2[4 * q + 3];
        a0 = ffma2(v0.x, w[8 * q],     a0);
        a1 = ffma2(v0.y, w[8 * q + 1], a1);
        a2 = ffma2(v1.x, w[8 * q + 2], a2);
        a3 = ffma2(v1.y, w[8 * q + 3], a3);
        a4 = ffma2(v2.x, w[8 * q + 4], a4);
        a5 = ffma2(v2.y, w[8 * q + 5], a5);
        a6 = ffma2(v3.x, w[8 * q + 6], a6);
        a7 = ffma2(v3.y, w[8 * q + 7], a7);
    }
    ull s = fadd2(fadd2(fadd2(a0, a1), fadd2(a2, a3)),
                  fadd2(fadd2(a4, a5), fadd2(a6, a7)));
    return fast_tanh(p + hsum2(s));
}

__global__ void __launch_bounds__(128, 2) scan_kernel(
    const float* __restrict__ Whh,
    float* __restrict__ outp)
{
    __shared__ __align__(16) float hs[2][HH];            // double-buffered h
    __shared__ __align__(16) float ps[2][STG_T * HH];    // staged pre
    const int j = threadIdx.x;
    const int b = blockIdx.x;

    const float* pre = g_pre + (size_t)b * TT * HH;

    // stages 0 and 1 in flight before the long-latency W load
    scan_prefetch(ps[0], pre, 0, j);
    CP_COMMIT();
    scan_prefetch(ps[1], pre, STG_T, j);
    CP_COMMIT();

    ull w[64];
    {
        const ulonglong2* wr = (const ulonglong2*)(Whh + j * HH);
#pragma unroll
        for (int q = 0; q < 32; q++) {
            ulonglong2 t = wr[q];
            w[2 * q]     = t.x;
            w[2 * q + 1] = t.y;
        }
    }

    float* out  = outp ? outp : g_out1;
    float* orow = out + (size_t)b * TT * HH + j;

    hs[0][j] = 0.0f;
    __syncthreads();

    const int nst = TT / STG_T;
#pragma unroll 1
    for (int s = 0; s < nst; s++) {
        const int buf = s & 1;
        if (s + 1 < nst) { CP_WAIT1(); } else { CP_WAIT0(); }
        __syncthreads();

        const float* pst = ps[buf];
        const int tbase = s * STG_T;
#pragma unroll 1
        for (int tl = 0; tl < STG_T; tl += 2) {
            {
                float hn = scan_step1(hs[0], w, pst[tl * HH + j]);
                hs[1][j] = hn;
                orow[(size_t)(tbase + tl) * HH] = hn;
                __syncthreads();
            }
            {
                float hn = scan_step1(hs[1], w, pst[(tl + 1) * HH + j]);
                hs[0][j] = hn;
                orow[(size_t)(tbase + tl + 1) * HH] = hn;
                __syncthreads();
            }
        }

        // refill stage s+2 into the buffer just consumed
        if (s + 2 < nst) {
            scan_prefetch(ps[buf], pre, (s + 2) * STG_T, j);
        }
        CP_COMMIT();
    }
}

// ---------------------------------------------------------------------------
extern "C" void kernel_launch(void* const* d_in, const int* in_sizes, int n_in,
                              void* d_out, int out_size)
{
    const float* x     = (const float*)d_in[0];
    const float* Wih0  = (const float*)d_in[1];
    const float* Whh0  = (const float*)d_in[2];
    const float* bih0  = (const float*)d_in[3];
    const float* bhh0  = (const float*)d_in[4];
    const float* Wih1  = (const float*)d_in[5];
    const float* Whh1  = (const float*)d_in[6];
    const float* bih1  = (const float*)d_in[7];
    const float* bhh1  = (const float*)d_in[8];
    float* out = (float*)d_out;

    // layer 0
    proj0_kernel<<<BB * TT / ROWS0, 128>>>(x, Wih0, bih0, bhh0);
    scan_kernel<<<BB, 128>>>(Whh0, nullptr);

    // layer 1
    proj1_kernel<<<PJ1_GRID, 128>>>(Wih1, bih1, bhh1);
    scan_kernel<<<BB, 128>>>(Whh1, out);
}